// round 12
// baseline (speedup 1.0000x reference)
#include <cuda_runtime.h>
#include <cuda_fp16.h>
#include <cstdint>

// Problem constants
#define B_   4
#define T_   2048
#define E_   1024
#define H_   16
#define HS_  64
#define DFF_ 4096
#define M_   (B_ * T_)   // 8192 rows

#define NSM_CTAS 296     // 2 CTAs per SM x 148 SMs

// ---------------------------------------------------------------------------
// Scratch (device globals)
// ---------------------------------------------------------------------------
__device__ __half g_a[(size_t)M_ * E_];
__device__ __half g_f[(size_t)M_ * DFF_];
__device__ __half g_q[(size_t)M_ * E_], g_k[(size_t)M_ * E_], g_v[(size_t)M_ * E_];
__device__ __half g_wq[(size_t)E_ * E_], g_wk[(size_t)E_ * E_];
__device__ __half g_wv[(size_t)E_ * E_], g_wp[(size_t)E_ * E_];
__device__ __half g_w1[(size_t)E_ * DFF_], g_w2[(size_t)DFF_ * E_];

// ---------------------------------------------------------------------------
// Helpers
// ---------------------------------------------------------------------------
__device__ __forceinline__ uint32_t smem_u32(const void* p) {
    uint32_t a;
    asm("{ .reg .u64 t; cvta.to.shared.u64 t, %1; cvt.u32.u64 %0, t; }"
        : "=r"(a) : "l"(p));
    return a;
}

__device__ __forceinline__ void ldm_x4(uint32_t* r, uint32_t addr) {
    asm volatile("ldmatrix.sync.aligned.m8n8.x4.shared.b16 {%0,%1,%2,%3}, [%4];"
                 : "=r"(r[0]), "=r"(r[1]), "=r"(r[2]), "=r"(r[3]) : "r"(addr));
}
__device__ __forceinline__ void ldm_x4_t(uint32_t* r, uint32_t addr) {
    asm volatile("ldmatrix.sync.aligned.m8n8.x4.trans.shared.b16 {%0,%1,%2,%3}, [%4];"
                 : "=r"(r[0]), "=r"(r[1]), "=r"(r[2]), "=r"(r[3]) : "r"(addr));
}

__device__ __forceinline__ void mma16816h(float* c, const uint32_t* a, const uint32_t* b) {
    asm volatile(
        "mma.sync.aligned.m16n8k16.row.col.f32.f16.f16.f32 "
        "{%0,%1,%2,%3}, {%4,%5,%6,%7}, {%8,%9}, {%0,%1,%2,%3};"
        : "+f"(c[0]), "+f"(c[1]), "+f"(c[2]), "+f"(c[3])
        : "r"(a[0]), "r"(a[1]), "r"(a[2]), "r"(a[3]), "r"(b[0]), "r"(b[1]));
}

#define CP_ASYNC16(dst, src) \
    asm volatile("cp.async.cg.shared.global [%0], [%1], 16;" :: "r"(dst), "l"(src))
#define CP_COMMIT() asm volatile("cp.async.commit_group;" ::: "memory")
#define CP_WAIT0() asm volatile("cp.async.wait_group 0;" ::: "memory")
#define CP_WAIT1() asm volatile("cp.async.wait_group 1;" ::: "memory")
#define CP_WAIT2() asm volatile("cp.async.wait_group 2;" ::: "memory")

__device__ __forceinline__ uint32_t pack_h2(float a, float b) {
    __half2 h = __floats2half2_rn(a, b);
    return *reinterpret_cast<uint32_t*>(&h);
}

// 128-row x 128-byte K-major tile, SW128 swizzle, 256 threads
__device__ __forceinline__ void cpa_tile128(const __half* __restrict__ g,
                                            int ldk, int k0, uint32_t sbase) {
    int tid = threadIdx.x;
    #pragma unroll
    for (int i = 0; i < 4; i++) {
        int idx = i * 256 + tid;
        int r = idx >> 3, c = idx & 7;
        uint32_t off = (uint32_t)(r * 128 + c * 16);
        off ^= (off >> 3) & 0x70;
        CP_ASYNC16(sbase + off, g + (size_t)r * ldk + k0 + c * 8);
    }
}

// 64-row x 128-byte tile (attention K/V), 256 threads
__device__ __forceinline__ void cpa_tile64(const __half* __restrict__ g,
                                           uint32_t sbase) {
    int tid = threadIdx.x;
    #pragma unroll
    for (int i = 0; i < 2; i++) {
        int idx = i * 256 + tid;
        int r = idx >> 3, c = idx & 7;
        uint32_t off = (uint32_t)(r * 128 + c * 16);
        off ^= (off >> 3) & 0x70;
        CP_ASYNC16(sbase + off, g + (size_t)r * E_ + c * 8);
    }
}

// ---------------------------------------------------------------------------
// Fused weight transpose+convert: 6 weights, one launch.
// ---------------------------------------------------------------------------
struct WtArgs {
    const float* src[6];
    __half* dst[6];
    int K[6], N[6];
    int base[6];
    int nx[6];
};

__global__ __launch_bounds__(256)
void wtrans_all_kernel(WtArgs a) {
    __shared__ float t[64][65];
    int bid = blockIdx.x;
    int z = 0;
    #pragma unroll
    for (int i = 1; i < 6; i++)
        if (bid >= a.base[i]) z = i;
    int local = bid - a.base[z];
    int bx = local % a.nx[z];
    int by = local / a.nx[z];
    const float* W = a.src[z];
    __half* T = a.dst[z];
    int K = a.K[z], N = a.N[z];
    int n0 = bx * 64, k0 = by * 64;

    int tid = threadIdx.x;
    int r = tid >> 2, c0 = (tid & 3) * 16;

    const float4* src = reinterpret_cast<const float4*>(
        W + (size_t)(k0 + r) * N + n0 + c0);
    #pragma unroll
    for (int j = 0; j < 4; j++) {
        float4 v = src[j];
        t[r][c0 + j * 4 + 0] = v.x;
        t[r][c0 + j * 4 + 1] = v.y;
        t[r][c0 + j * 4 + 2] = v.z;
        t[r][c0 + j * 4 + 3] = v.w;
    }
    __syncthreads();

    int nr = tid >> 2;
    uint32_t o8[8];
    #pragma unroll
    for (int j = 0; j < 8; j++)
        o8[j] = pack_h2(t[c0 + 2 * j][nr], t[c0 + 2 * j + 1][nr]);
    __half* dst = T + (size_t)(n0 + nr) * K + k0 + c0;
    *reinterpret_cast<uint4*>(dst)     = make_uint4(o8[0], o8[1], o8[2], o8[3]);
    *reinterpret_cast<uint4*>(dst + 8) = make_uint4(o8[4], o8[5], o8[6], o8[7]);
}

// ---------------------------------------------------------------------------
// LayerNorm -> fp16
// ---------------------------------------------------------------------------
__global__ __launch_bounds__(256)
void ln_h_kernel(const float* __restrict__ in, const float* __restrict__ gamma,
                 const float* __restrict__ beta, __half* __restrict__ O) {
    int row = blockIdx.x;
    int t = threadIdx.x;
    float4 v = ((const float4*)(in + (size_t)row * E_))[t];

    float s1 = v.x + v.y + v.z + v.w;
    float s2 = v.x * v.x + v.y * v.y + v.z * v.z + v.w * v.w;
    #pragma unroll
    for (int o = 16; o > 0; o >>= 1) {
        s1 += __shfl_xor_sync(0xffffffffu, s1, o);
        s2 += __shfl_xor_sync(0xffffffffu, s2, o);
    }
    __shared__ float red[64];
    int lane = t & 31, w = t >> 5;
    if (lane == 0) { red[w] = s1; red[w + 32] = s2; }
    __syncthreads();
    float ts1 = 0.f, ts2 = 0.f;
    #pragma unroll
    for (int i = 0; i < 8; i++) { ts1 += red[i]; ts2 += red[i + 32]; }

    float mu  = ts1 * (1.0f / E_);
    float var = ts2 * (1.0f / E_) - mu * mu;
    float rs  = rsqrtf(var + 1e-5f);

    float4 g4 = ((const float4*)gamma)[t];
    float4 b4 = ((const float4*)beta)[t];
    float o0 = (v.x - mu) * rs * g4.x + b4.x;
    float o1 = (v.y - mu) * rs * g4.y + b4.y;
    float o2 = (v.z - mu) * rs * g4.z + b4.z;
    float o3 = (v.w - mu) * rs * g4.w + b4.w;

    size_t idx = (size_t)row * E_ + t * 4;
    *reinterpret_cast<uint2*>(O + idx) = make_uint2(pack_h2(o0, o1), pack_h2(o2, o3));
}

// ---------------------------------------------------------------------------
// Continuous-pipeline persistent fp16 GEMM.
// Each CTA streams (tile, k-chunk) iterations through a 3-stage pipeline with
// no drain at tile boundaries; epilogue overlaps in-flight loads.
// EPI: 0 = bias -> fp16 ; 1 = bias+relu -> fp16 ; 2 = bias+res -> fp32
// ---------------------------------------------------------------------------
#define HTILE_B  16384
#define HSTAGE_B (2 * HTILE_B)
#define HGSMEM   (3 * HSTAGE_B + 128)

template<int EPI>
__global__ __launch_bounds__(256, 2)
void hgemm_kernel(const __half* __restrict__ A, const __half* __restrict__ Bw,
                  const float* __restrict__ bias, const float* __restrict__ res,
                  float* __restrict__ Cf, __half* __restrict__ Hh,
                  int M, int N, int K) {
    extern __shared__ char dsm[];
    uint32_t base = smem_u32(dsm);
    base = (base + 127) & ~127u;

    int ntN = N >> 7;
    int ntiles = (M >> 7) * ntN;
    int G = gridDim.x;
    int t0 = blockIdx.x;
    if (t0 >= ntiles) return;
    int NT = K >> 6;
    int cnt = (ntiles - t0 + G - 1) / G;
    int total = cnt * NT;

    int tid = threadIdx.x, lane = tid & 31, wid = tid >> 5;
    int warp_m = wid >> 2, warp_n = wid & 3;
    int amat = lane >> 3, arin = lane & 7;
    int aRow = warp_m * 64 + (amat & 1) * 8 + arin;
    int aChk = amat >> 1;
    int bRow4 = warp_n * 32 + ((lane >> 4) & 1) * 8 + (lane & 7);
    int bChk4 = (lane >> 3) & 1;
    int gq = lane >> 2, tig = lane & 3;

    // ---- load cursor (2 iterations ahead) ----
    int tL = t0, ktL = 0;
    uint32_t stageL = 0;
    const __half* AbL = A + (size_t)((tL / ntN) << 7) * K;
    const __half* BbL = Bw + (size_t)((tL % ntN) << 7) * K;

    auto load_step = [&]() {
        uint32_t s = base + stageL * HSTAGE_B;
        cpa_tile128(AbL, K, ktL << 6, s);
        cpa_tile128(BbL, K, ktL << 6, s + HTILE_B);
        CP_COMMIT();
        stageL = (stageL == 2) ? 0 : stageL + 1;
        if (++ktL == NT) {
            ktL = 0;
            tL += G;
            if (tL < ntiles) {
                AbL = A + (size_t)((tL / ntN) << 7) * K;
                BbL = Bw + (size_t)((tL % ntN) << 7) * K;
            }
        }
    };

    load_step();
    if (total > 1) load_step();

    float C[4][4][4];
    #pragma unroll
    for (int i = 0; i < 4; i++)
        #pragma unroll
        for (int j = 0; j < 4; j++)
            #pragma unroll
            for (int r = 0; r < 4; r++) C[i][j][r] = 0.f;

    // ---- compute cursor ----
    uint32_t stageC = 0;
    int tC = t0, ktC = 0;
    int m0 = (tC / ntN) << 7, n0 = (tC % ntN) << 7;

    for (int g = 0; g < total; ++g) {
        if (g + 1 < total) { CP_WAIT1(); } else { CP_WAIT0(); }
        __syncthreads();

        uint32_t sc = base + stageC * HSTAGE_B;
        uint32_t sA = sc, sB = sc + HTILE_B;

        #pragma unroll
        for (int ks = 0; ks < 4; ks++) {
            uint32_t a4[4][4], b4[2][4];
            #pragma unroll
            for (int mi = 0; mi < 4; mi++) {
                uint32_t off = (uint32_t)((aRow + mi * 16) * 128 + (aChk + ks * 2) * 16);
                off ^= (off >> 3) & 0x70;
                ldm_x4(a4[mi], sA + off);
            }
            #pragma unroll
            for (int ni2 = 0; ni2 < 2; ni2++) {
                uint32_t off = (uint32_t)((bRow4 + ni2 * 16) * 128 + (bChk4 + ks * 2) * 16);
                off ^= (off >> 3) & 0x70;
                ldm_x4(b4[ni2], sB + off);
            }
            #pragma unroll
            for (int mi = 0; mi < 4; mi++) {
                #pragma unroll
                for (int ni2 = 0; ni2 < 2; ni2++) {
                    mma16816h(C[mi][2 * ni2],     a4[mi], &b4[ni2][0]);
                    mma16816h(C[mi][2 * ni2 + 1], a4[mi], &b4[ni2][2]);
                }
            }
        }
        stageC = (stageC == 2) ? 0 : stageC + 1;

        if (g + 2 < total) load_step();

        if (++ktC == NT) {
            // ---- epilogue for tile tC (overlaps in-flight loads) ----
            #pragma unroll
            for (int mi = 0; mi < 4; mi++) {
                #pragma unroll
                for (int ni = 0; ni < 4; ni++) {
                    int m = m0 + warp_m * 64 + mi * 16 + gq;
                    int n = n0 + warp_n * 32 + ni * 8 + tig * 2;
                    float2 bv = *reinterpret_cast<const float2*>(&bias[n]);
                    #pragma unroll
                    for (int half_ = 0; half_ < 2; half_++) {
                        int row = m + half_ * 8;
                        float a0 = C[mi][ni][half_ * 2 + 0] + bv.x;
                        float a1 = C[mi][ni][half_ * 2 + 1] + bv.y;
                        size_t o = (size_t)row * N + n;
                        if (EPI == 0) {
                            *reinterpret_cast<uint32_t*>(Hh + o) = pack_h2(a0, a1);
                        } else if (EPI == 1) {
                            a0 = fmaxf(a0, 0.f); a1 = fmaxf(a1, 0.f);
                            *reinterpret_cast<uint32_t*>(Hh + o) = pack_h2(a0, a1);
                        } else {
                            float2 rv = *reinterpret_cast<const float2*>(&res[o]);
                            a0 += rv.x; a1 += rv.y;
                            *reinterpret_cast<float2*>(&Cf[o]) = make_float2(a0, a1);
                        }
                    }
                }
            }
            ktC = 0;
            tC += G;
            if (tC < ntiles) { m0 = (tC / ntN) << 7; n0 = (tC % ntN) << 7; }
            #pragma unroll
            for (int i = 0; i < 4; i++)
                #pragma unroll
                for (int j = 0; j < 4; j++)
                    #pragma unroll
                    for (int r = 0; r < 4; r++) C[i][j][r] = 0.f;
        }
    }
}

// ---------------------------------------------------------------------------
// Continuous-pipeline persistent fused QKV (z folded into the tile stream)
// ---------------------------------------------------------------------------
struct QKVArgs {
    const __half* w[3];
    const float* bias[3];
    __half* o[3];
};

__global__ __launch_bounds__(256, 2)
void qkv_kernel(const __half* __restrict__ A, QKVArgs args) {
    extern __shared__ char dsm[];
    uint32_t base = smem_u32(dsm);
    base = (base + 127) & ~127u;

    const int ntN = E_ >> 7;           // 8
    const int per = (M_ >> 7) * ntN;   // 512
    const int ntiles = 3 * per;        // 1536
    const int NT = E_ >> 6;            // 16
    int G = gridDim.x;
    int t0 = blockIdx.x;
    if (t0 >= ntiles) return;
    int cnt = (ntiles - t0 + G - 1) / G;
    int total = cnt * NT;

    int tid = threadIdx.x, lane = tid & 31, wid = tid >> 5;
    int warp_m = wid >> 2, warp_n = wid & 3;
    int amat = lane >> 3, arin = lane & 7;
    int aRow = warp_m * 64 + (amat & 1) * 8 + arin;
    int aChk = amat >> 1;
    int bRow4 = warp_n * 32 + ((lane >> 4) & 1) * 8 + (lane & 7);
    int bChk4 = (lane >> 3) & 1;
    int gq = lane >> 2, tig = lane & 3;

    // ---- load cursor ----
    int tL = t0, ktL = 0;
    uint32_t stageL = 0;
    int zL = tL / per, lL = tL - zL * per;
    const __half* AbL = A + (size_t)((lL >> 3) << 7) * E_;
    const __half* BbL = args.w[zL] + (size_t)((lL & 7) << 7) * E_;

    auto load_step = [&]() {
        uint32_t s = base + stageL * HSTAGE_B;
        cpa_tile128(AbL, E_, ktL << 6, s);
        cpa_tile128(BbL, E_, ktL << 6, s + HTILE_B);
        CP_COMMIT();
        stageL = (stageL == 2) ? 0 : stageL + 1;
        if (++ktL == NT) {
            ktL = 0;
            tL += G;
            if (tL < ntiles) {
                zL = tL / per; lL = tL - zL * per;
                AbL = A + (size_t)((lL >> 3) << 7) * E_;
                BbL = args.w[zL] + (size_t)((lL & 7) << 7) * E_;
            }
        }
    };

    load_step();
    if (total > 1) load_step();

    float C[4][4][4];
    #pragma unroll
    for (int i = 0; i < 4; i++)
        #pragma unroll
        for (int j = 0; j < 4; j++)
            #pragma unroll
            for (int r = 0; r < 4; r++) C[i][j][r] = 0.f;

    uint32_t stageC = 0;
    int tC = t0, ktC = 0;
    int zC = tC / per, lC = tC - zC * per;
    int m0 = (lC >> 3) << 7, n0 = (lC & 7) << 7;

    for (int g = 0; g < total; ++g) {
        if (g + 1 < total) { CP_WAIT1(); } else { CP_WAIT0(); }
        __syncthreads();

        uint32_t sc = base + stageC * HSTAGE_B;
        uint32_t sA = sc, sB = sc + HTILE_B;

        #pragma unroll
        for (int ks = 0; ks < 4; ks++) {
            uint32_t a4[4][4], b4[2][4];
            #pragma unroll
            for (int mi = 0; mi < 4; mi++) {
                uint32_t off = (uint32_t)((aRow + mi * 16) * 128 + (aChk + ks * 2) * 16);
                off ^= (off >> 3) & 0x70;
                ldm_x4(a4[mi], sA + off);
            }
            #pragma unroll
            for (int ni2 = 0; ni2 < 2; ni2++) {
                uint32_t off = (uint32_t)((bRow4 + ni2 * 16) * 128 + (bChk4 + ks * 2) * 16);
                off ^= (off >> 3) & 0x70;
                ldm_x4(b4[ni2], sB + off);
            }
            #pragma unroll
            for (int mi = 0; mi < 4; mi++) {
                #pragma unroll
                for (int ni2 = 0; ni2 < 2; ni2++) {
                    mma16816h(C[mi][2 * ni2],     a4[mi], &b4[ni2][0]);
                    mma16816h(C[mi][2 * ni2 + 1], a4[mi], &b4[ni2][2]);
                }
            }
        }
        stageC = (stageC == 2) ? 0 : stageC + 1;

        if (g + 2 < total) load_step();

        if (++ktC == NT) {
            const float* bias = args.bias[zC];
            __half* Hh = args.o[zC];
            #pragma unroll
            for (int mi = 0; mi < 4; mi++) {
                #pragma unroll
                for (int ni = 0; ni < 4; ni++) {
                    int m = m0 + warp_m * 64 + mi * 16 + gq;
                    int n = n0 + warp_n * 32 + ni * 8 + tig * 2;
                    float2 bv = *reinterpret_cast<const float2*>(&bias[n]);
                    #pragma unroll
                    for (int half_ = 0; half_ < 2; half_++) {
                        int row = m + half_ * 8;
                        float a0 = C[mi][ni][half_ * 2 + 0] + bv.x;
                        float a1 = C[mi][ni][half_ * 2 + 1] + bv.y;
                        size_t o = (size_t)row * E_ + n;
                        *reinterpret_cast<uint32_t*>(Hh + o) = pack_h2(a0, a1);
                    }
                }
            }
            ktC = 0;
            tC += G;
            if (tC < ntiles) {
                zC = tC / per; lC = tC - zC * per;
                m0 = (lC >> 3) << 7; n0 = (lC & 7) << 7;
            }
            #pragma unroll
            for (int i = 0; i < 4; i++)
                #pragma unroll
                for (int j = 0; j < 4; j++)
                    #pragma unroll
                    for (int r = 0; r < 4; r++) C[i][j][r] = 0.f;
        }
    }
}

// ---------------------------------------------------------------------------
// fp16 tensor-core causal flash attention (unchanged from R10/R11)
// ---------------------------------------------------------------------------
#define AQ_BYTES  16384
#define AST_SZ    16384
#define ATTN_SMEM (AQ_BYTES + 3 * AST_SZ + 128)
#define CEXP 0.18033688011112042f  // 0.125 * log2(e)

__global__ __launch_bounds__(256, 2)
void attn_mma_kernel(const __half* __restrict__ Qg, const __half* __restrict__ Kg,
                     const __half* __restrict__ Vg, __half* __restrict__ O) {
    extern __shared__ char dsm[];
    uint32_t base = smem_u32(dsm);
    base = (base + 127) & ~127u;

    int tid = threadIdx.x, lane = tid & 31, w = tid >> 5;
    int gq = lane >> 2, tig = lane & 3;
    int qi = gridDim.x - 1 - blockIdx.x;
    int q0 = qi * 128;
    int bh = blockIdx.y;
    int b = bh >> 4, h = bh & 15;
    size_t gbase = ((size_t)b * T_) * E_ + (size_t)h * HS_;

    int nt = (q0 >> 6) + 2;

    cpa_tile128(Qg + gbase + (size_t)q0 * E_, E_, 0, base);
    CP_COMMIT();
    #pragma unroll
    for (int st = 0; st < 2; st++) {
        uint32_t s = base + AQ_BYTES + st * AST_SZ;
        size_t koff = gbase + (size_t)(st * 64) * E_;
        cpa_tile64(Kg + koff, s);
        cpa_tile64(Vg + koff, s + 8192);
        CP_COMMIT();
    }

    CP_WAIT2();
    __syncthreads();

    uint32_t qf[4][4];
    {
        int arow = w * 16 + (lane & 7) + ((lane & 8) ? 8 : 0);
        int asel = (lane >> 4) & 1;
        #pragma unroll
        for (int ks = 0; ks < 4; ks++) {
            uint32_t off = (uint32_t)(arow * 128 + (ks * 2 + asel) * 16);
            off ^= (off >> 3) & 0x70;
            ldm_x4(qf[ks], base + off);
        }
    }

    float Oa[8][4];
    #pragma unroll
    for (int s = 0; s < 8; s++)
        #pragma unroll
        for (int r = 0; r < 4; r++) Oa[s][r] = 0.f;
    float l0r = 0.f, l1r = 0.f;

    int kRowBase = (lane & 7) + ((lane >= 16) ? 8 : 0);
    int kChkSel  = (lane & 8) ? 1 : 0;
    int vRowBase = (lane & 7) + ((lane & 8) ? 8 : 0);
    int vColB    = ((lane >= 16) ? 16 : 0);

    int maskFrom = q0 >> 6;

    for (int jt = 0; jt < nt; jt++) {
        if (jt + 1 < nt) { CP_WAIT1(); } else { CP_WAIT0(); }
        __syncthreads();

        bool act = !(jt == nt - 1 && w < 4);

        uint32_t sc = base + AQ_BYTES + (jt % 3) * AST_SZ;
        uint32_t sK = sc, sV = sc + 8192;

        if (act) {
            float S[8][4];
            #pragma unroll
            for (int s = 0; s < 8; s++)
                #pragma unroll
                for (int r = 0; r < 4; r++) S[s][r] = 0.f;

            #pragma unroll
            for (int ks = 0; ks < 4; ks++) {
                #pragma unroll
                for (int g = 0; g < 4; g++) {
                    uint32_t k4[4];
                    uint32_t off = (uint32_t)((g * 16 + kRowBase) * 128 +
                                              (ks * 2 + kChkSel) * 16);
                    off ^= (off >> 3) & 0x70;
                    ldm_x4(k4, sK + off);
                    mma16816h(S[2 * g],     qf[ks], &k4[0]);
                    mma16816h(S[2 * g + 1], qf[ks], &k4[2]);
                }
            }

            if (jt >= maskFrom) {
                int qr0 = q0 + w * 16 + gq;
                int kc0 = jt * 64 + 2 * tig;
                #pragma unroll
                for (int s = 0; s < 8; s++) {
                    int kc = kc0 + s * 8;
                    if (kc     > qr0)     S[s][0] = -1e30f;
                    if (kc + 1 > qr0)     S[s][1] = -1e30f;
                    if (kc     > qr0 + 8) S[s][2] = -1e30f;
                    if (kc + 1 > qr0 + 8) S[s][3] = -1e30f;
                }
            }

            uint32_t pa[4][4];
            float ls0 = 0.f, ls1 = 0.f;
            #pragma unroll
            for (int kk = 0; kk < 4; kk++) {
                #pragma unroll
                for (int half_ = 0; half_ < 2; half_++) {
                    float* Sr = S[2 * kk + half_];
                    __half2 e0 = h2exp2(__floats2half2_rn(Sr[0] * CEXP, Sr[1] * CEXP));
                    __half2 e1 = h2exp2(__floats2half2_rn(Sr[2] * CEXP, Sr[3] * CEXP));
                    pa[kk][half_ * 2 + 0] = *reinterpret_cast<uint32_t*>(&e0);
                    pa[kk][half_ * 2 + 1] = *reinterpret_cast<uint32_t*>(&e1);
                    float2 f0 = __half22float2(e0);
                    float2 f1 = __half22float2(e1);
                    ls0 += f0.x + f0.y;
                    ls1 += f1.x + f1.y;
                }
            }
            l0r += ls0;
            l1r += ls1;

            #pragma unroll
            for (int kk = 0; kk < 4; kk++) {
                #pragma unroll
                for (int g = 0; g < 4; g++) {
                    uint32_t v4[4];
                    uint32_t off = (uint32_t)((kk * 16 + vRowBase) * 128 +
                                              g * 32 + vColB);
                    off ^= (off >> 3) & 0x70;
                    ldm_x4_t(v4, sV + off);
                    mma16816h(Oa[2 * g],     pa[kk], &v4[0]);
                    mma16816h(Oa[2 * g + 1], pa[kk], &v4[2]);
                }
            }
        }

        if (jt + 2 < nt) {
            uint32_t sn = base + AQ_BYTES + ((jt + 2) % 3) * AST_SZ;
            size_t koff = gbase + (size_t)((jt + 2) * 64) * E_;
            cpa_tile64(Kg + koff, sn);
            cpa_tile64(Vg + koff, sn + 8192);
            CP_COMMIT();
        }
    }

    l0r += __shfl_xor_sync(0xffffffffu, l0r, 1);
    l0r += __shfl_xor_sync(0xffffffffu, l0r, 2);
    l1r += __shfl_xor_sync(0xffffffffu, l1r, 1);
    l1r += __shfl_xor_sync(0xffffffffu, l1r, 2);

    float inv0 = 1.0f / l0r, inv1 = 1.0f / l1r;
    int row0 = q0 + w * 16 + gq;
    #pragma unroll
    for (int s = 0; s < 8; s++) {
        int col = s * 8 + 2 * tig;
        size_t o0 = gbase + (size_t)row0 * E_ + col;
        size_t o1 = gbase + (size_t)(row0 + 8) * E_ + col;
        *reinterpret_cast<uint32_t*>(O + o0) = pack_h2(Oa[s][0] * inv0, Oa[s][1] * inv0);
        *reinterpret_cast<uint32_t*>(O + o1) = pack_h2(Oa[s][2] * inv1, Oa[s][3] * inv1);
    }
}

// ---------------------------------------------------------------------------
// Launch
// ---------------------------------------------------------------------------
extern "C" void kernel_launch(void* const* d_in, const int* in_sizes, int n_in,
                              void* d_out, int out_size) {
    (void)in_sizes; (void)n_in; (void)out_size;
    const float* x     = (const float*)d_in[0];
    const float* ln1_g = (const float*)d_in[1];
    const float* ln1_b = (const float*)d_in[2];
    const float* Wq    = (const float*)d_in[3];
    const float* bq    = (const float*)d_in[4];
    const float* Wk    = (const float*)d_in[5];
    const float* bk    = (const float*)d_in[6];
    const float* Wv    = (const float*)d_in[7];
    const float* bv    = (const float*)d_in[8];
    const float* Wp    = (const float*)d_in[9];
    const float* bp    = (const float*)d_in[10];
    const float* ln2_g = (const float*)d_in[11];
    const float* ln2_b = (const float*)d_in[12];
    const float* W1    = (const float*)d_in[13];
    const float* b1    = (const float*)d_in[14];
    const float* W2    = (const float*)d_in[15];
    const float* b2    = (const float*)d_in[16];
    float* out = (float*)d_out;

    __half *a, *f, *q, *k, *v, *wq, *wk, *wv, *wp, *w1, *w2;
    cudaGetSymbolAddress((void**)&a, g_a);
    cudaGetSymbolAddress((void**)&f, g_f);
    cudaGetSymbolAddress((void**)&q, g_q);
    cudaGetSymbolAddress((void**)&k, g_k);
    cudaGetSymbolAddress((void**)&v, g_v);
    cudaGetSymbolAddress((void**)&wq, g_wq);
    cudaGetSymbolAddress((void**)&wk, g_wk);
    cudaGetSymbolAddress((void**)&wv, g_wv);
    cudaGetSymbolAddress((void**)&wp, g_wp);
    cudaGetSymbolAddress((void**)&w1, g_w1);
    cudaGetSymbolAddress((void**)&w2, g_w2);

    cudaFuncSetAttribute(attn_mma_kernel,
                         cudaFuncAttributeMaxDynamicSharedMemorySize, ATTN_SMEM);
    cudaFuncSetAttribute(hgemm_kernel<1>,
                         cudaFuncAttributeMaxDynamicSharedMemorySize, HGSMEM);
    cudaFuncSetAttribute(hgemm_kernel<2>,
                         cudaFuncAttributeMaxDynamicSharedMemorySize, HGSMEM);
    cudaFuncSetAttribute(qkv_kernel,
                         cudaFuncAttributeMaxDynamicSharedMemorySize, HGSMEM);

    WtArgs wa;
    wa.src[0] = Wq; wa.dst[0] = wq; wa.K[0] = E_;   wa.N[0] = E_;   wa.base[0] = 0;    wa.nx[0] = 16;
    wa.src[1] = Wk; wa.dst[1] = wk; wa.K[1] = E_;   wa.N[1] = E_;   wa.base[1] = 256;  wa.nx[1] = 16;
    wa.src[2] = Wv; wa.dst[2] = wv; wa.K[2] = E_;   wa.N[2] = E_;   wa.base[2] = 512;  wa.nx[2] = 16;
    wa.src[3] = Wp; wa.dst[3] = wp; wa.K[3] = E_;   wa.N[3] = E_;   wa.base[3] = 768;  wa.nx[3] = 16;
    wa.src[4] = W1; wa.dst[4] = w1; wa.K[4] = E_;   wa.N[4] = DFF_; wa.base[4] = 1024; wa.nx[4] = 64;
    wa.src[5] = W2; wa.dst[5] = w2; wa.K[5] = DFF_; wa.N[5] = E_;   wa.base[5] = 2048; wa.nx[5] = 16;
    wtrans_all_kernel<<<3072, 256>>>(wa);

    // ln1 -> fp16
    ln_h_kernel<<<M_, 256>>>(x, ln1_g, ln1_b, a);

    // persistent fused QKV (continuous pipeline)
    QKVArgs qa;
    qa.w[0] = wq; qa.bias[0] = bq; qa.o[0] = q;
    qa.w[1] = wk; qa.bias[1] = bk; qa.o[1] = k;
    qa.w[2] = wv; qa.bias[2] = bv; qa.o[2] = v;
    qkv_kernel<<<NSM_CTAS, 256, HGSMEM>>>(a, qa);

    // attention -> a
    dim3 gA(T_ / 128, B_ * H_);
    attn_mma_kernel<<<gA, 256, ATTN_SMEM>>>(q, k, v, a);

    // proj + residual -> out (fp32), persistent
    hgemm_kernel<2><<<NSM_CTAS, 256, HGSMEM>>>(a, wp, bp, x, out, nullptr,
                                               M_, E_, E_);

    // ln2 -> fp16
    ln_h_kernel<<<M_, 256>>>(out, ln2_g, ln2_b, a);

    // FFN1 (relu -> fp16), persistent
    hgemm_kernel<1><<<NSM_CTAS, 256, HGSMEM>>>(a, w1, b1, nullptr, nullptr, f,
                                               M_, DFF_, E_);

    // FFN2 + residual (in place on out), persistent
    hgemm_kernel<2><<<NSM_CTAS, 256, HGSMEM>>>(f, w2, b2, out, out, nullptr,
                                               M_, E_, DFF_);
}

// round 13
// speedup vs baseline: 1.0704x; 1.0704x over previous
#include <cuda_runtime.h>
#include <cuda_fp16.h>
#include <cstdint>

// Problem constants
#define B_   4
#define T_   2048
#define E_   1024
#define H_   16
#define HS_  64
#define DFF_ 4096
#define M_   (B_ * T_)   // 8192 rows

// ---------------------------------------------------------------------------
// Scratch (device globals)
// ---------------------------------------------------------------------------
__device__ __half g_a[(size_t)M_ * E_];     // fp16 activations
__device__ __half g_f[(size_t)M_ * DFF_];   // fp16 FFN hidden
__device__ __half g_q[(size_t)M_ * E_], g_k[(size_t)M_ * E_], g_v[(size_t)M_ * E_];
// fp16 transposed weights [N,K]
__device__ __half g_wq[(size_t)E_ * E_], g_wk[(size_t)E_ * E_];
__device__ __half g_wv[(size_t)E_ * E_], g_wp[(size_t)E_ * E_];
__device__ __half g_w1[(size_t)E_ * DFF_], g_w2[(size_t)DFF_ * E_];

// ---------------------------------------------------------------------------
// Helpers
// ---------------------------------------------------------------------------
__device__ __forceinline__ uint32_t smem_u32(const void* p) {
    uint32_t a;
    asm("{ .reg .u64 t; cvta.to.shared.u64 t, %1; cvt.u32.u64 %0, t; }"
        : "=r"(a) : "l"(p));
    return a;
}

__device__ __forceinline__ void ldm_x4(uint32_t* r, uint32_t addr) {
    asm volatile("ldmatrix.sync.aligned.m8n8.x4.shared.b16 {%0,%1,%2,%3}, [%4];"
                 : "=r"(r[0]), "=r"(r[1]), "=r"(r[2]), "=r"(r[3]) : "r"(addr));
}
__device__ __forceinline__ void ldm_x4_t(uint32_t* r, uint32_t addr) {
    asm volatile("ldmatrix.sync.aligned.m8n8.x4.trans.shared.b16 {%0,%1,%2,%3}, [%4];"
                 : "=r"(r[0]), "=r"(r[1]), "=r"(r[2]), "=r"(r[3]) : "r"(addr));
}

__device__ __forceinline__ void mma16816h(float* c, const uint32_t* a, const uint32_t* b) {
    asm volatile(
        "mma.sync.aligned.m16n8k16.row.col.f32.f16.f16.f32 "
        "{%0,%1,%2,%3}, {%4,%5,%6,%7}, {%8,%9}, {%0,%1,%2,%3};"
        : "+f"(c[0]), "+f"(c[1]), "+f"(c[2]), "+f"(c[3])
        : "r"(a[0]), "r"(a[1]), "r"(a[2]), "r"(a[3]), "r"(b[0]), "r"(b[1]));
}

#define CP_ASYNC16(dst, src) \
    asm volatile("cp.async.cg.shared.global [%0], [%1], 16;" :: "r"(dst), "l"(src))
#define CP_COMMIT() asm volatile("cp.async.commit_group;" ::: "memory")
#define CP_WAIT0() asm volatile("cp.async.wait_group 0;" ::: "memory")
#define CP_WAIT1() asm volatile("cp.async.wait_group 1;" ::: "memory")
#define CP_WAIT2() asm volatile("cp.async.wait_group 2;" ::: "memory")

__device__ __forceinline__ uint32_t pack_h2(float a, float b) {
    __half2 h = __floats2half2_rn(a, b);
    return *reinterpret_cast<uint32_t*>(&h);
}

// 128-row x 128-byte K-major tile, SW128 swizzle, 256 threads
__device__ __forceinline__ void cpa_tile128(const __half* __restrict__ g,
                                            int ldk, int k0, uint32_t sbase) {
    int tid = threadIdx.x;
    #pragma unroll
    for (int i = 0; i < 4; i++) {
        int idx = i * 256 + tid;
        int r = idx >> 3, c = idx & 7;
        uint32_t off = (uint32_t)(r * 128 + c * 16);
        off ^= (off >> 3) & 0x70;
        CP_ASYNC16(sbase + off, g + (size_t)r * ldk + k0 + c * 8);
    }
}

// 64-row x 128-byte tile (attention K/V), 256 threads
__device__ __forceinline__ void cpa_tile64(const __half* __restrict__ g,
                                           uint32_t sbase) {
    int tid = threadIdx.x;
    #pragma unroll
    for (int i = 0; i < 2; i++) {
        int idx = i * 256 + tid;
        int r = idx >> 3, c = idx & 7;
        uint32_t off = (uint32_t)(r * 128 + c * 16);
        off ^= (off >> 3) & 0x70;
        CP_ASYNC16(sbase + off, g + (size_t)r * E_ + c * 8);
    }
}

// ---------------------------------------------------------------------------
// Fused weight transpose+convert: 6 weights, one launch.
// ---------------------------------------------------------------------------
struct WtArgs {
    const float* src[6];
    __half* dst[6];
    int K[6], N[6];
    int base[6];
    int nx[6];
};

__global__ __launch_bounds__(256)
void wtrans_all_kernel(WtArgs a) {
    __shared__ float t[64][65];
    int bid = blockIdx.x;
    int z = 0;
    #pragma unroll
    for (int i = 1; i < 6; i++)
        if (bid >= a.base[i]) z = i;
    int local = bid - a.base[z];
    int bx = local % a.nx[z];
    int by = local / a.nx[z];
    const float* W = a.src[z];
    __half* T = a.dst[z];
    int K = a.K[z], N = a.N[z];
    int n0 = bx * 64, k0 = by * 64;

    int tid = threadIdx.x;
    int r = tid >> 2, c0 = (tid & 3) * 16;

    const float4* src = reinterpret_cast<const float4*>(
        W + (size_t)(k0 + r) * N + n0 + c0);
    #pragma unroll
    for (int j = 0; j < 4; j++) {
        float4 v = src[j];
        t[r][c0 + j * 4 + 0] = v.x;
        t[r][c0 + j * 4 + 1] = v.y;
        t[r][c0 + j * 4 + 2] = v.z;
        t[r][c0 + j * 4 + 3] = v.w;
    }
    __syncthreads();

    int nr = tid >> 2;
    uint32_t o8[8];
    #pragma unroll
    for (int j = 0; j < 8; j++)
        o8[j] = pack_h2(t[c0 + 2 * j][nr], t[c0 + 2 * j + 1][nr]);
    __half* dst = T + (size_t)(n0 + nr) * K + k0 + c0;
    *reinterpret_cast<uint4*>(dst)     = make_uint4(o8[0], o8[1], o8[2], o8[3]);
    *reinterpret_cast<uint4*>(dst + 8) = make_uint4(o8[4], o8[5], o8[6], o8[7]);
}

// ---------------------------------------------------------------------------
// LayerNorm fp32-in -> fp16
// ---------------------------------------------------------------------------
__global__ __launch_bounds__(256)
void ln_h_kernel(const float* __restrict__ in, const float* __restrict__ gamma,
                 const float* __restrict__ beta, __half* __restrict__ O) {
    int row = blockIdx.x;
    int t = threadIdx.x;
    float4 v = ((const float4*)(in + (size_t)row * E_))[t];

    float s1 = v.x + v.y + v.z + v.w;
    float s2 = v.x * v.x + v.y * v.y + v.z * v.z + v.w * v.w;
    #pragma unroll
    for (int o = 16; o > 0; o >>= 1) {
        s1 += __shfl_xor_sync(0xffffffffu, s1, o);
        s2 += __shfl_xor_sync(0xffffffffu, s2, o);
    }
    __shared__ float red[64];
    int lane = t & 31, w = t >> 5;
    if (lane == 0) { red[w] = s1; red[w + 32] = s2; }
    __syncthreads();
    float ts1 = 0.f, ts2 = 0.f;
    #pragma unroll
    for (int i = 0; i < 8; i++) { ts1 += red[i]; ts2 += red[i + 32]; }

    float mu  = ts1 * (1.0f / E_);
    float var = ts2 * (1.0f / E_) - mu * mu;
    float rs  = rsqrtf(var + 1e-5f);

    float4 g4 = ((const float4*)gamma)[t];
    float4 b4 = ((const float4*)beta)[t];
    float o0 = (v.x - mu) * rs * g4.x + b4.x;
    float o1 = (v.y - mu) * rs * g4.y + b4.y;
    float o2 = (v.z - mu) * rs * g4.z + b4.z;
    float o3 = (v.w - mu) * rs * g4.w + b4.w;

    size_t idx = (size_t)row * E_ + t * 4;
    *reinterpret_cast<uint2*>(O + idx) = make_uint2(pack_h2(o0, o1), pack_h2(o2, o3));
}

// ---------------------------------------------------------------------------
// LayerNorm fp16-in -> fp16 (for the fp16 residual stream)
// ---------------------------------------------------------------------------
__global__ __launch_bounds__(256)
void ln_h16_kernel(const __half* __restrict__ in, const float* __restrict__ gamma,
                   const float* __restrict__ beta, __half* __restrict__ O) {
    int row = blockIdx.x;
    int t = threadIdx.x;
    uint2 pv = ((const uint2*)(in + (size_t)row * E_))[t];
    float2 f01 = __half22float2(*reinterpret_cast<__half2*>(&pv.x));
    float2 f23 = __half22float2(*reinterpret_cast<__half2*>(&pv.y));
    float vx = f01.x, vy = f01.y, vz = f23.x, vw = f23.y;

    float s1 = vx + vy + vz + vw;
    float s2 = vx * vx + vy * vy + vz * vz + vw * vw;
    #pragma unroll
    for (int o = 16; o > 0; o >>= 1) {
        s1 += __shfl_xor_sync(0xffffffffu, s1, o);
        s2 += __shfl_xor_sync(0xffffffffu, s2, o);
    }
    __shared__ float red[64];
    int lane = t & 31, w = t >> 5;
    if (lane == 0) { red[w] = s1; red[w + 32] = s2; }
    __syncthreads();
    float ts1 = 0.f, ts2 = 0.f;
    #pragma unroll
    for (int i = 0; i < 8; i++) { ts1 += red[i]; ts2 += red[i + 32]; }

    float mu  = ts1 * (1.0f / E_);
    float var = ts2 * (1.0f / E_) - mu * mu;
    float rs  = rsqrtf(var + 1e-5f);

    float4 g4 = ((const float4*)gamma)[t];
    float4 b4 = ((const float4*)beta)[t];
    float o0 = (vx - mu) * rs * g4.x + b4.x;
    float o1 = (vy - mu) * rs * g4.y + b4.y;
    float o2 = (vz - mu) * rs * g4.z + b4.z;
    float o3 = (vw - mu) * rs * g4.w + b4.w;

    size_t idx = (size_t)row * E_ + t * 4;
    *reinterpret_cast<uint2*>(O + idx) = make_uint2(pack_h2(o0, o1), pack_h2(o2, o3));
}

// ---------------------------------------------------------------------------
// fp16 GEMM (R10 config): C[M,N] = A[M,K] @ Wt[N,K]^T + bias (+...)
// 128x128 CTA, BK=64, 8 warps (2x4), 3-stage cp.async, 2 CTAs/SM.
// EPI: 0 bias->fp16 ; 1 bias+relu->fp16 ; 3 bias+res(fp32)->fp16 ;
//      4 bias+res(fp16)->fp32
// ---------------------------------------------------------------------------
#define HTILE_B  16384
#define HSTAGE_B (2 * HTILE_B)
#define HGSMEM   (3 * HSTAGE_B + 128)

template<int EPI>
__device__ __forceinline__ void gemm_core_h(
        const __half* __restrict__ A, const __half* __restrict__ Bw,
        const float* __restrict__ bias, const float* __restrict__ resf,
        const __half* __restrict__ res16,
        float* __restrict__ Cf, __half* __restrict__ Hh,
        int M, int N, int K, int m0, int n0, uint32_t base) {
    int tid = threadIdx.x, lane = tid & 31, wid = tid >> 5;
    int warp_m = wid >> 2;
    int warp_n = wid & 3;

    const __half* Ab = A  + (size_t)m0 * K;
    const __half* Bb = Bw + (size_t)n0 * K;

    int amat = lane >> 3, arin = lane & 7;
    int aRow = warp_m * 64 + (amat & 1) * 8 + arin;
    int aChk = amat >> 1;
    int bRow4 = warp_n * 32 + ((lane >> 4) & 1) * 8 + (lane & 7);
    int bChk4 = (lane >> 3) & 1;

    float C[4][4][4];
    #pragma unroll
    for (int i = 0; i < 4; i++)
        #pragma unroll
        for (int j = 0; j < 4; j++)
            #pragma unroll
            for (int r = 0; r < 4; r++) C[i][j][r] = 0.f;

    int NT = K >> 6;

    cpa_tile128(Ab, K, 0, base);
    cpa_tile128(Bb, K, 0, base + HTILE_B);
    CP_COMMIT();
    cpa_tile128(Ab, K, 64, base + HSTAGE_B);
    cpa_tile128(Bb, K, 64, base + HSTAGE_B + HTILE_B);
    CP_COMMIT();

    for (int kt = 0; kt < NT; kt++) {
        if (kt + 1 < NT) { CP_WAIT1(); } else { CP_WAIT0(); }
        __syncthreads();

        uint32_t sc = base + (kt % 3) * HSTAGE_B;
        uint32_t sA = sc, sB = sc + HTILE_B;

        #pragma unroll
        for (int ks = 0; ks < 4; ks++) {
            uint32_t a4[4][4], b4[2][4];
            #pragma unroll
            for (int mi = 0; mi < 4; mi++) {
                uint32_t off = (uint32_t)((aRow + mi * 16) * 128 + (aChk + ks * 2) * 16);
                off ^= (off >> 3) & 0x70;
                ldm_x4(a4[mi], sA + off);
            }
            #pragma unroll
            for (int ni2 = 0; ni2 < 2; ni2++) {
                uint32_t off = (uint32_t)((bRow4 + ni2 * 16) * 128 + (bChk4 + ks * 2) * 16);
                off ^= (off >> 3) & 0x70;
                ldm_x4(b4[ni2], sB + off);
            }
            #pragma unroll
            for (int mi = 0; mi < 4; mi++) {
                #pragma unroll
                for (int ni2 = 0; ni2 < 2; ni2++) {
                    mma16816h(C[mi][2 * ni2],     a4[mi], &b4[ni2][0]);
                    mma16816h(C[mi][2 * ni2 + 1], a4[mi], &b4[ni2][2]);
                }
            }
        }

        if (kt + 2 < NT) {
            uint32_t sn = base + ((kt + 2) % 3) * HSTAGE_B;
            int k0 = (kt + 2) << 6;
            cpa_tile128(Ab, K, k0, sn);
            cpa_tile128(Bb, K, k0, sn + HTILE_B);
            CP_COMMIT();
        }
    }

    int gq = lane >> 2, tig = lane & 3;
    #pragma unroll
    for (int mi = 0; mi < 4; mi++) {
        #pragma unroll
        for (int ni = 0; ni < 4; ni++) {
            int m = m0 + warp_m * 64 + mi * 16 + gq;
            int n = n0 + warp_n * 32 + ni * 8 + tig * 2;
            float2 bv = *reinterpret_cast<const float2*>(&bias[n]);
            #pragma unroll
            for (int half_ = 0; half_ < 2; half_++) {
                int row = m + half_ * 8;
                float a0 = C[mi][ni][half_ * 2 + 0] + bv.x;
                float a1 = C[mi][ni][half_ * 2 + 1] + bv.y;
                size_t o = (size_t)row * N + n;
                if (EPI == 0) {
                    *reinterpret_cast<uint32_t*>(Hh + o) = pack_h2(a0, a1);
                } else if (EPI == 1) {
                    a0 = fmaxf(a0, 0.f); a1 = fmaxf(a1, 0.f);
                    *reinterpret_cast<uint32_t*>(Hh + o) = pack_h2(a0, a1);
                } else if (EPI == 3) {
                    float2 rv = *reinterpret_cast<const float2*>(&resf[o]);
                    a0 += rv.x; a1 += rv.y;
                    *reinterpret_cast<uint32_t*>(Hh + o) = pack_h2(a0, a1);
                } else {  // EPI == 4
                    uint32_t rp = *reinterpret_cast<const uint32_t*>(&res16[o]);
                    float2 rv = __half22float2(*reinterpret_cast<__half2*>(&rp));
                    a0 += rv.x; a1 += rv.y;
                    *reinterpret_cast<float2*>(&Cf[o]) = make_float2(a0, a1);
                }
            }
        }
    }
}

template<int EPI>
__global__ __launch_bounds__(256, 2)
void hgemm_kernel(const __half* __restrict__ A, const __half* __restrict__ Bw,
                  const float* __restrict__ bias, const float* __restrict__ resf,
                  const __half* __restrict__ res16,
                  float* __restrict__ Cf, __half* __restrict__ Hh,
                  int M, int N, int K) {
    extern __shared__ char dsm[];
    uint32_t base = smem_u32(dsm);
    base = (base + 127) & ~127u;
    gemm_core_h<EPI>(A, Bw, bias, resf, res16, Cf, Hh, M, N, K,
                     blockIdx.y * 128, blockIdx.x * 128, base);
}

struct QKVArgs {
    const __half* w[3];
    const float* bias[3];
    __half* o[3];
};

__global__ __launch_bounds__(256, 2)
void qkv_kernel(const __half* __restrict__ A, QKVArgs args) {
    extern __shared__ char dsm[];
    uint32_t base = smem_u32(dsm);
    base = (base + 127) & ~127u;
    int z = blockIdx.z;
    gemm_core_h<0>(A, args.w[z], args.bias[z], nullptr, nullptr, nullptr,
                   args.o[z], M_, E_, E_,
                   blockIdx.y * 128, blockIdx.x * 128, base);
}

// ---------------------------------------------------------------------------
// fp16 tensor-core causal flash attention (R10: no running max, warp skip)
// ---------------------------------------------------------------------------
#define AQ_BYTES  16384
#define AST_SZ    16384
#define ATTN_SMEM (AQ_BYTES + 3 * AST_SZ + 128)
#define CEXP 0.18033688011112042f  // 0.125 * log2(e)

__global__ __launch_bounds__(256, 2)
void attn_mma_kernel(const __half* __restrict__ Qg, const __half* __restrict__ Kg,
                     const __half* __restrict__ Vg, __half* __restrict__ O) {
    extern __shared__ char dsm[];
    uint32_t base = smem_u32(dsm);
    base = (base + 127) & ~127u;

    int tid = threadIdx.x, lane = tid & 31, w = tid >> 5;
    int gq = lane >> 2, tig = lane & 3;
    int qi = gridDim.x - 1 - blockIdx.x;
    int q0 = qi * 128;
    int bh = blockIdx.y;
    int b = bh >> 4, h = bh & 15;
    size_t gbase = ((size_t)b * T_) * E_ + (size_t)h * HS_;

    int nt = (q0 >> 6) + 2;

    cpa_tile128(Qg + gbase + (size_t)q0 * E_, E_, 0, base);
    CP_COMMIT();
    #pragma unroll
    for (int st = 0; st < 2; st++) {
        uint32_t s = base + AQ_BYTES + st * AST_SZ;
        size_t koff = gbase + (size_t)(st * 64) * E_;
        cpa_tile64(Kg + koff, s);
        cpa_tile64(Vg + koff, s + 8192);
        CP_COMMIT();
    }

    CP_WAIT2();
    __syncthreads();

    uint32_t qf[4][4];
    {
        int arow = w * 16 + (lane & 7) + ((lane & 8) ? 8 : 0);
        int asel = (lane >> 4) & 1;
        #pragma unroll
        for (int ks = 0; ks < 4; ks++) {
            uint32_t off = (uint32_t)(arow * 128 + (ks * 2 + asel) * 16);
            off ^= (off >> 3) & 0x70;
            ldm_x4(qf[ks], base + off);
        }
    }

    float Oa[8][4];
    #pragma unroll
    for (int s = 0; s < 8; s++)
        #pragma unroll
        for (int r = 0; r < 4; r++) Oa[s][r] = 0.f;
    float l0r = 0.f, l1r = 0.f;

    int kRowBase = (lane & 7) + ((lane >= 16) ? 8 : 0);
    int kChkSel  = (lane & 8) ? 1 : 0;
    int vRowBase = (lane & 7) + ((lane & 8) ? 8 : 0);
    int vColB    = ((lane >= 16) ? 16 : 0);

    int maskFrom = q0 >> 6;

    for (int jt = 0; jt < nt; jt++) {
        if (jt + 1 < nt) { CP_WAIT1(); } else { CP_WAIT0(); }
        __syncthreads();

        bool act = !(jt == nt - 1 && w < 4);

        uint32_t sc = base + AQ_BYTES + (jt % 3) * AST_SZ;
        uint32_t sK = sc, sV = sc + 8192;

        if (act) {
            float S[8][4];
            #pragma unroll
            for (int s = 0; s < 8; s++)
                #pragma unroll
                for (int r = 0; r < 4; r++) S[s][r] = 0.f;

            #pragma unroll
            for (int ks = 0; ks < 4; ks++) {
                #pragma unroll
                for (int g = 0; g < 4; g++) {
                    uint32_t k4[4];
                    uint32_t off = (uint32_t)((g * 16 + kRowBase) * 128 +
                                              (ks * 2 + kChkSel) * 16);
                    off ^= (off >> 3) & 0x70;
                    ldm_x4(k4, sK + off);
                    mma16816h(S[2 * g],     qf[ks], &k4[0]);
                    mma16816h(S[2 * g + 1], qf[ks], &k4[2]);
                }
            }

            if (jt >= maskFrom) {
                int qr0 = q0 + w * 16 + gq;
                int kc0 = jt * 64 + 2 * tig;
                #pragma unroll
                for (int s = 0; s < 8; s++) {
                    int kc = kc0 + s * 8;
                    if (kc     > qr0)     S[s][0] = -1e30f;
                    if (kc + 1 > qr0)     S[s][1] = -1e30f;
                    if (kc     > qr0 + 8) S[s][2] = -1e30f;
                    if (kc + 1 > qr0 + 8) S[s][3] = -1e30f;
                }
            }

            uint32_t pa[4][4];
            float ls0 = 0.f, ls1 = 0.f;
            #pragma unroll
            for (int kk = 0; kk < 4; kk++) {
                #pragma unroll
                for (int half_ = 0; half_ < 2; half_++) {
                    float* Sr = S[2 * kk + half_];
                    __half2 e0 = h2exp2(__floats2half2_rn(Sr[0] * CEXP, Sr[1] * CEXP));
                    __half2 e1 = h2exp2(__floats2half2_rn(Sr[2] * CEXP, Sr[3] * CEXP));
                    pa[kk][half_ * 2 + 0] = *reinterpret_cast<uint32_t*>(&e0);
                    pa[kk][half_ * 2 + 1] = *reinterpret_cast<uint32_t*>(&e1);
                    float2 f0 = __half22float2(e0);
                    float2 f1 = __half22float2(e1);
                    ls0 += f0.x + f0.y;
                    ls1 += f1.x + f1.y;
                }
            }
            l0r += ls0;
            l1r += ls1;

            #pragma unroll
            for (int kk = 0; kk < 4; kk++) {
                #pragma unroll
                for (int g = 0; g < 4; g++) {
                    uint32_t v4[4];
                    uint32_t off = (uint32_t)((kk * 16 + vRowBase) * 128 +
                                              g * 32 + vColB);
                    off ^= (off >> 3) & 0x70;
                    ldm_x4_t(v4, sV + off);
                    mma16816h(Oa[2 * g],     pa[kk], &v4[0]);
                    mma16816h(Oa[2 * g + 1], pa[kk], &v4[2]);
                }
            }
        }

        if (jt + 2 < nt) {
            uint32_t sn = base + AQ_BYTES + ((jt + 2) % 3) * AST_SZ;
            size_t koff = gbase + (size_t)((jt + 2) * 64) * E_;
            cpa_tile64(Kg + koff, sn);
            cpa_tile64(Vg + koff, sn + 8192);
            CP_COMMIT();
        }
    }

    l0r += __shfl_xor_sync(0xffffffffu, l0r, 1);
    l0r += __shfl_xor_sync(0xffffffffu, l0r, 2);
    l1r += __shfl_xor_sync(0xffffffffu, l1r, 1);
    l1r += __shfl_xor_sync(0xffffffffu, l1r, 2);

    float inv0 = 1.0f / l0r, inv1 = 1.0f / l1r;
    int row0 = q0 + w * 16 + gq;
    #pragma unroll
    for (int s = 0; s < 8; s++) {
        int col = s * 8 + 2 * tig;
        size_t o0 = gbase + (size_t)row0 * E_ + col;
        size_t o1 = gbase + (size_t)(row0 + 8) * E_ + col;
        *reinterpret_cast<uint32_t*>(O + o0) = pack_h2(Oa[s][0] * inv0, Oa[s][1] * inv0);
        *reinterpret_cast<uint32_t*>(O + o1) = pack_h2(Oa[s][2] * inv1, Oa[s][3] * inv1);
    }
}

// ---------------------------------------------------------------------------
// Launch
// ---------------------------------------------------------------------------
extern "C" void kernel_launch(void* const* d_in, const int* in_sizes, int n_in,
                              void* d_out, int out_size) {
    (void)in_sizes; (void)n_in; (void)out_size;
    const float* x     = (const float*)d_in[0];
    const float* ln1_g = (const float*)d_in[1];
    const float* ln1_b = (const float*)d_in[2];
    const float* Wq    = (const float*)d_in[3];
    const float* bq    = (const float*)d_in[4];
    const float* Wk    = (const float*)d_in[5];
    const float* bk    = (const float*)d_in[6];
    const float* Wv    = (const float*)d_in[7];
    const float* bv    = (const float*)d_in[8];
    const float* Wp    = (const float*)d_in[9];
    const float* bp    = (const float*)d_in[10];
    const float* ln2_g = (const float*)d_in[11];
    const float* ln2_b = (const float*)d_in[12];
    const float* W1    = (const float*)d_in[13];
    const float* b1    = (const float*)d_in[14];
    const float* W2    = (const float*)d_in[15];
    const float* b2    = (const float*)d_in[16];
    float* out = (float*)d_out;

    __half *a, *f, *q, *k, *v, *wq, *wk, *wv, *wp, *w1, *w2;
    cudaGetSymbolAddress((void**)&a, g_a);
    cudaGetSymbolAddress((void**)&f, g_f);
    cudaGetSymbolAddress((void**)&q, g_q);
    cudaGetSymbolAddress((void**)&k, g_k);
    cudaGetSymbolAddress((void**)&v, g_v);
    cudaGetSymbolAddress((void**)&wq, g_wq);
    cudaGetSymbolAddress((void**)&wk, g_wk);
    cudaGetSymbolAddress((void**)&wv, g_wv);
    cudaGetSymbolAddress((void**)&wp, g_wp);
    cudaGetSymbolAddress((void**)&w1, g_w1);
    cudaGetSymbolAddress((void**)&w2, g_w2);

    // r1 = fp16 residual stream buffer (g_q is free after attention)
    __half* r1 = q;

    cudaFuncSetAttribute(attn_mma_kernel,
                         cudaFuncAttributeMaxDynamicSharedMemorySize, ATTN_SMEM);
    cudaFuncSetAttribute(hgemm_kernel<1>,
                         cudaFuncAttributeMaxDynamicSharedMemorySize, HGSMEM);
    cudaFuncSetAttribute(hgemm_kernel<3>,
                         cudaFuncAttributeMaxDynamicSharedMemorySize, HGSMEM);
    cudaFuncSetAttribute(hgemm_kernel<4>,
                         cudaFuncAttributeMaxDynamicSharedMemorySize, HGSMEM);
    cudaFuncSetAttribute(qkv_kernel,
                         cudaFuncAttributeMaxDynamicSharedMemorySize, HGSMEM);

    WtArgs wa;
    wa.src[0] = Wq; wa.dst[0] = wq; wa.K[0] = E_;   wa.N[0] = E_;   wa.base[0] = 0;    wa.nx[0] = 16;
    wa.src[1] = Wk; wa.dst[1] = wk; wa.K[1] = E_;   wa.N[1] = E_;   wa.base[1] = 256;  wa.nx[1] = 16;
    wa.src[2] = Wv; wa.dst[2] = wv; wa.K[2] = E_;   wa.N[2] = E_;   wa.base[2] = 512;  wa.nx[2] = 16;
    wa.src[3] = Wp; wa.dst[3] = wp; wa.K[3] = E_;   wa.N[3] = E_;   wa.base[3] = 768;  wa.nx[3] = 16;
    wa.src[4] = W1; wa.dst[4] = w1; wa.K[4] = E_;   wa.N[4] = DFF_; wa.base[4] = 1024; wa.nx[4] = 64;
    wa.src[5] = W2; wa.dst[5] = w2; wa.K[5] = DFF_; wa.N[5] = E_;   wa.base[5] = 2048; wa.nx[5] = 16;
    wtrans_all_kernel<<<3072, 256>>>(wa);

    // ln1 -> fp16
    ln_h_kernel<<<M_, 256>>>(x, ln1_g, ln1_b, a);

    // fused QKV
    QKVArgs qa;
    qa.w[0] = wq; qa.bias[0] = bq; qa.o[0] = q;
    qa.w[1] = wk; qa.bias[1] = bk; qa.o[1] = k;
    qa.w[2] = wv; qa.bias[2] = bv; qa.o[2] = v;
    dim3 gQKV(E_ / 128, M_ / 128, 3);
    qkv_kernel<<<gQKV, 256, HGSMEM>>>(a, qa);

    // attention -> a
    dim3 gA(T_ / 128, B_ * H_);
    attn_mma_kernel<<<gA, 256, ATTN_SMEM>>>(q, k, v, a);

    // proj + residual(x fp32) -> r1 (fp16 residual stream; overwrites g_q
    // AFTER attention has consumed it)
    dim3 gE(E_ / 128, M_ / 128);
    hgemm_kernel<3><<<gE, 256, HGSMEM>>>(a, wp, bp, x, nullptr, nullptr, r1,
                                         M_, E_, E_);

    // ln2 (fp16 in) -> fp16
    ln_h16_kernel<<<M_, 256>>>(r1, ln2_g, ln2_b, a);

    // FFN1 (relu -> fp16)
    dim3 gF1(DFF_ / 128, M_ / 128);
    hgemm_kernel<1><<<gF1, 256, HGSMEM>>>(a, w1, b1, nullptr, nullptr, nullptr, f,
                                          M_, DFF_, E_);

    // FFN2 + residual(r1 fp16) -> out (fp32)
    hgemm_kernel<4><<<gE, 256, HGSMEM>>>(f, w2, b2, nullptr, r1, out, nullptr,
                                         M_, E_, DFF_);
}

// round 14
// speedup vs baseline: 1.0809x; 1.0098x over previous
#include <cuda_runtime.h>
#include <cuda_fp16.h>
#include <cstdint>

// Problem constants
#define B_   4
#define T_   2048
#define E_   1024
#define H_   16
#define HS_  64
#define DFF_ 4096
#define M_   (B_ * T_)   // 8192 rows

// ---------------------------------------------------------------------------
// Scratch (device globals)
// ---------------------------------------------------------------------------
__device__ __half g_a[(size_t)M_ * E_];     // fp16 activations
__device__ __half g_f[(size_t)M_ * DFF_];   // fp16 FFN hidden
__device__ __half g_q[(size_t)M_ * E_], g_k[(size_t)M_ * E_], g_v[(size_t)M_ * E_];
// fp16 transposed weights [N,K]
__device__ __half g_wq[(size_t)E_ * E_], g_wk[(size_t)E_ * E_];
__device__ __half g_wv[(size_t)E_ * E_], g_wp[(size_t)E_ * E_];
__device__ __half g_w1[(size_t)E_ * DFF_], g_w2[(size_t)DFF_ * E_];

// ---------------------------------------------------------------------------
// Helpers
// ---------------------------------------------------------------------------
__device__ __forceinline__ uint32_t smem_u32(const void* p) {
    uint32_t a;
    asm("{ .reg .u64 t; cvta.to.shared.u64 t, %1; cvt.u32.u64 %0, t; }"
        : "=r"(a) : "l"(p));
    return a;
}

__device__ __forceinline__ void ldm_x4(uint32_t* r, uint32_t addr) {
    asm volatile("ldmatrix.sync.aligned.m8n8.x4.shared.b16 {%0,%1,%2,%3}, [%4];"
                 : "=r"(r[0]), "=r"(r[1]), "=r"(r[2]), "=r"(r[3]) : "r"(addr));
}
__device__ __forceinline__ void ldm_x4_t(uint32_t* r, uint32_t addr) {
    asm volatile("ldmatrix.sync.aligned.m8n8.x4.trans.shared.b16 {%0,%1,%2,%3}, [%4];"
                 : "=r"(r[0]), "=r"(r[1]), "=r"(r[2]), "=r"(r[3]) : "r"(addr));
}

__device__ __forceinline__ void mma16816h(float* c, const uint32_t* a, const uint32_t* b) {
    asm volatile(
        "mma.sync.aligned.m16n8k16.row.col.f32.f16.f16.f32 "
        "{%0,%1,%2,%3}, {%4,%5,%6,%7}, {%8,%9}, {%0,%1,%2,%3};"
        : "+f"(c[0]), "+f"(c[1]), "+f"(c[2]), "+f"(c[3])
        : "r"(a[0]), "r"(a[1]), "r"(a[2]), "r"(a[3]), "r"(b[0]), "r"(b[1]));
}

#define CP_ASYNC16(dst, src) \
    asm volatile("cp.async.cg.shared.global [%0], [%1], 16;" :: "r"(dst), "l"(src))
#define CP_COMMIT() asm volatile("cp.async.commit_group;" ::: "memory")
#define CP_WAIT0() asm volatile("cp.async.wait_group 0;" ::: "memory")
#define CP_WAIT1() asm volatile("cp.async.wait_group 1;" ::: "memory")
#define CP_WAIT2() asm volatile("cp.async.wait_group 2;" ::: "memory")

__device__ __forceinline__ uint32_t pack_h2(float a, float b) {
    __half2 h = __floats2half2_rn(a, b);
    return *reinterpret_cast<uint32_t*>(&h);
}

// 128-row x 128-byte K-major tile, SW128 swizzle, 256 threads
__device__ __forceinline__ void cpa_tile128(const __half* __restrict__ g,
                                            int ldk, int k0, uint32_t sbase) {
    int tid = threadIdx.x;
    #pragma unroll
    for (int i = 0; i < 4; i++) {
        int idx = i * 256 + tid;
        int r = idx >> 3, c = idx & 7;
        uint32_t off = (uint32_t)(r * 128 + c * 16);
        off ^= (off >> 3) & 0x70;
        CP_ASYNC16(sbase + off, g + (size_t)r * ldk + k0 + c * 8);
    }
}

// ---------------------------------------------------------------------------
// LN body (shared by prep kernel and fp16-in LN)
// ---------------------------------------------------------------------------
__device__ __forceinline__ void ln_body(float vx, float vy, float vz, float vw,
                                        const float* __restrict__ gamma,
                                        const float* __restrict__ beta,
                                        __half* __restrict__ O, int row, int t,
                                        float* red) {
    float s1 = vx + vy + vz + vw;
    float s2 = vx * vx + vy * vy + vz * vz + vw * vw;
    #pragma unroll
    for (int o = 16; o > 0; o >>= 1) {
        s1 += __shfl_xor_sync(0xffffffffu, s1, o);
        s2 += __shfl_xor_sync(0xffffffffu, s2, o);
    }
    int lane = t & 31, w = t >> 5;
    if (lane == 0) { red[w] = s1; red[w + 32] = s2; }
    __syncthreads();
    float ts1 = 0.f, ts2 = 0.f;
    #pragma unroll
    for (int i = 0; i < 8; i++) { ts1 += red[i]; ts2 += red[i + 32]; }

    float mu  = ts1 * (1.0f / E_);
    float var = ts2 * (1.0f / E_) - mu * mu;
    float rs  = rsqrtf(var + 1e-5f);

    float4 g4 = ((const float4*)gamma)[t];
    float4 b4 = ((const float4*)beta)[t];
    float o0 = (vx - mu) * rs * g4.x + b4.x;
    float o1 = (vy - mu) * rs * g4.y + b4.y;
    float o2 = (vz - mu) * rs * g4.z + b4.z;
    float o3 = (vw - mu) * rs * g4.w + b4.w;

    size_t idx = (size_t)row * E_ + t * 4;
    *reinterpret_cast<uint2*>(O + idx) = make_uint2(pack_h2(o0, o1), pack_h2(o2, o3));
}

// ---------------------------------------------------------------------------
// Fused prep: blocks [0,3072) = weight transpose+convert; [3072,..) = ln1.
// ---------------------------------------------------------------------------
struct PrepArgs {
    const float* src[6];
    __half* dst[6];
    int K[6], N[6];
    int base[6];
    int nx[6];
    const float* x;
    const float* ln_g;
    const float* ln_b;
    __half* ln_o;
};

#define WT_BLOCKS 3072

__global__ __launch_bounds__(256)
void prep_kernel(PrepArgs a) {
    __shared__ float t[64][65];
    int bid = blockIdx.x;
    int tid = threadIdx.x;

    if (bid >= WT_BLOCKS) {
        // ---- ln1 ----
        int row = bid - WT_BLOCKS;
        float4 v = ((const float4*)(a.x + (size_t)row * E_))[tid];
        ln_body(v.x, v.y, v.z, v.w, a.ln_g, a.ln_b, a.ln_o, row, tid, &t[0][0]);
        return;
    }

    // ---- weight transpose ----
    int z = 0;
    #pragma unroll
    for (int i = 1; i < 6; i++)
        if (bid >= a.base[i]) z = i;
    int local = bid - a.base[z];
    int bx = local % a.nx[z];
    int by = local / a.nx[z];
    const float* W = a.src[z];
    __half* T = a.dst[z];
    int K = a.K[z], N = a.N[z];
    int n0 = bx * 64, k0 = by * 64;

    int r = tid >> 2, c0 = (tid & 3) * 16;
    const float4* src = reinterpret_cast<const float4*>(
        W + (size_t)(k0 + r) * N + n0 + c0);
    #pragma unroll
    for (int j = 0; j < 4; j++) {
        float4 v = src[j];
        t[r][c0 + j * 4 + 0] = v.x;
        t[r][c0 + j * 4 + 1] = v.y;
        t[r][c0 + j * 4 + 2] = v.z;
        t[r][c0 + j * 4 + 3] = v.w;
    }
    __syncthreads();

    int nr = tid >> 2;
    uint32_t o8[8];
    #pragma unroll
    for (int j = 0; j < 8; j++)
        o8[j] = pack_h2(t[c0 + 2 * j][nr], t[c0 + 2 * j + 1][nr]);
    __half* dst = T + (size_t)(n0 + nr) * K + k0 + c0;
    *reinterpret_cast<uint4*>(dst)     = make_uint4(o8[0], o8[1], o8[2], o8[3]);
    *reinterpret_cast<uint4*>(dst + 8) = make_uint4(o8[4], o8[5], o8[6], o8[7]);
}

// ---------------------------------------------------------------------------
// LayerNorm fp16-in -> fp16 (residual stream)
// ---------------------------------------------------------------------------
__global__ __launch_bounds__(256)
void ln_h16_kernel(const __half* __restrict__ in, const float* __restrict__ gamma,
                   const float* __restrict__ beta, __half* __restrict__ O) {
    __shared__ float red[64];
    int row = blockIdx.x;
    int t = threadIdx.x;
    uint2 pv = ((const uint2*)(in + (size_t)row * E_))[t];
    float2 f01 = __half22float2(*reinterpret_cast<__half2*>(&pv.x));
    float2 f23 = __half22float2(*reinterpret_cast<__half2*>(&pv.y));
    ln_body(f01.x, f01.y, f23.x, f23.y, gamma, beta, O, row, t, red);
}

// ---------------------------------------------------------------------------
// fp16 GEMM (R13 config): C[M,N] = A[M,K] @ Wt[N,K]^T + bias (+...)
// EPI: 0 bias->fp16 ; 1 bias+relu->fp16 ; 3 bias+res(fp32)->fp16 ;
//      4 bias+res(fp16)->fp32
// ---------------------------------------------------------------------------
#define HTILE_B  16384
#define HSTAGE_B (2 * HTILE_B)
#define HGSMEM   (3 * HSTAGE_B + 128)

template<int EPI>
__device__ __forceinline__ void gemm_core_h(
        const __half* __restrict__ A, const __half* __restrict__ Bw,
        const float* __restrict__ bias, const float* __restrict__ resf,
        const __half* __restrict__ res16,
        float* __restrict__ Cf, __half* __restrict__ Hh,
        int M, int N, int K, int m0, int n0, uint32_t base) {
    int tid = threadIdx.x, lane = tid & 31, wid = tid >> 5;
    int warp_m = wid >> 2;
    int warp_n = wid & 3;

    const __half* Ab = A  + (size_t)m0 * K;
    const __half* Bb = Bw + (size_t)n0 * K;

    int amat = lane >> 3, arin = lane & 7;
    int aRow = warp_m * 64 + (amat & 1) * 8 + arin;
    int aChk = amat >> 1;
    int bRow4 = warp_n * 32 + ((lane >> 4) & 1) * 8 + (lane & 7);
    int bChk4 = (lane >> 3) & 1;

    float C[4][4][4];
    #pragma unroll
    for (int i = 0; i < 4; i++)
        #pragma unroll
        for (int j = 0; j < 4; j++)
            #pragma unroll
            for (int r = 0; r < 4; r++) C[i][j][r] = 0.f;

    int NT = K >> 6;

    cpa_tile128(Ab, K, 0, base);
    cpa_tile128(Bb, K, 0, base + HTILE_B);
    CP_COMMIT();
    cpa_tile128(Ab, K, 64, base + HSTAGE_B);
    cpa_tile128(Bb, K, 64, base + HSTAGE_B + HTILE_B);
    CP_COMMIT();

    for (int kt = 0; kt < NT; kt++) {
        if (kt + 1 < NT) { CP_WAIT1(); } else { CP_WAIT0(); }
        __syncthreads();

        uint32_t sc = base + (kt % 3) * HSTAGE_B;
        uint32_t sA = sc, sB = sc + HTILE_B;

        #pragma unroll
        for (int ks = 0; ks < 4; ks++) {
            uint32_t a4[4][4], b4[2][4];
            #pragma unroll
            for (int mi = 0; mi < 4; mi++) {
                uint32_t off = (uint32_t)((aRow + mi * 16) * 128 + (aChk + ks * 2) * 16);
                off ^= (off >> 3) & 0x70;
                ldm_x4(a4[mi], sA + off);
            }
            #pragma unroll
            for (int ni2 = 0; ni2 < 2; ni2++) {
                uint32_t off = (uint32_t)((bRow4 + ni2 * 16) * 128 + (bChk4 + ks * 2) * 16);
                off ^= (off >> 3) & 0x70;
                ldm_x4(b4[ni2], sB + off);
            }
            #pragma unroll
            for (int mi = 0; mi < 4; mi++) {
                #pragma unroll
                for (int ni2 = 0; ni2 < 2; ni2++) {
                    mma16816h(C[mi][2 * ni2],     a4[mi], &b4[ni2][0]);
                    mma16816h(C[mi][2 * ni2 + 1], a4[mi], &b4[ni2][2]);
                }
            }
        }

        if (kt + 2 < NT) {
            uint32_t sn = base + ((kt + 2) % 3) * HSTAGE_B;
            int k0 = (kt + 2) << 6;
            cpa_tile128(Ab, K, k0, sn);
            cpa_tile128(Bb, K, k0, sn + HTILE_B);
            CP_COMMIT();
        }
    }

    int gq = lane >> 2, tig = lane & 3;
    #pragma unroll
    for (int mi = 0; mi < 4; mi++) {
        #pragma unroll
        for (int ni = 0; ni < 4; ni++) {
            int m = m0 + warp_m * 64 + mi * 16 + gq;
            int n = n0 + warp_n * 32 + ni * 8 + tig * 2;
            float2 bv = *reinterpret_cast<const float2*>(&bias[n]);
            #pragma unroll
            for (int half_ = 0; half_ < 2; half_++) {
                int row = m + half_ * 8;
                float a0 = C[mi][ni][half_ * 2 + 0] + bv.x;
                float a1 = C[mi][ni][half_ * 2 + 1] + bv.y;
                size_t o = (size_t)row * N + n;
                if (EPI == 0) {
                    *reinterpret_cast<uint32_t*>(Hh + o) = pack_h2(a0, a1);
                } else if (EPI == 1) {
                    a0 = fmaxf(a0, 0.f); a1 = fmaxf(a1, 0.f);
                    *reinterpret_cast<uint32_t*>(Hh + o) = pack_h2(a0, a1);
                } else if (EPI == 3) {
                    float2 rv = *reinterpret_cast<const float2*>(&resf[o]);
                    a0 += rv.x; a1 += rv.y;
                    *reinterpret_cast<uint32_t*>(Hh + o) = pack_h2(a0, a1);
                } else {  // EPI == 4
                    uint32_t rp = *reinterpret_cast<const uint32_t*>(&res16[o]);
                    float2 rv = __half22float2(*reinterpret_cast<__half2*>(&rp));
                    a0 += rv.x; a1 += rv.y;
                    *reinterpret_cast<float2*>(&Cf[o]) = make_float2(a0, a1);
                }
            }
        }
    }
}

template<int EPI>
__global__ __launch_bounds__(256, 2)
void hgemm_kernel(const __half* __restrict__ A, const __half* __restrict__ Bw,
                  const float* __restrict__ bias, const float* __restrict__ resf,
                  const __half* __restrict__ res16,
                  float* __restrict__ Cf, __half* __restrict__ Hh,
                  int M, int N, int K) {
    extern __shared__ char dsm[];
    uint32_t base = smem_u32(dsm);
    base = (base + 127) & ~127u;
    gemm_core_h<EPI>(A, Bw, bias, resf, res16, Cf, Hh, M, N, K,
                     blockIdx.y * 128, blockIdx.x * 128, base);
}

struct QKVArgs {
    const __half* w[3];
    const float* bias[3];
    __half* o[3];
};

__global__ __launch_bounds__(256, 2)
void qkv_kernel(const __half* __restrict__ A, QKVArgs args) {
    extern __shared__ char dsm[];
    uint32_t base = smem_u32(dsm);
    base = (base + 127) & ~127u;
    int z = blockIdx.z;
    gemm_core_h<0>(A, args.w[z], args.bias[z], nullptr, nullptr, nullptr,
                   args.o[z], M_, E_, E_,
                   blockIdx.y * 128, blockIdx.x * 128, base);
}

// ---------------------------------------------------------------------------
// fp16 tensor-core causal flash attention.
// q-tile 128, 8 warps, 128-key k-tiles processed as two 64-col halves
// (registers reused), 3-stage KV pipe, 2 CTA/SM, no running max.
// smem: Q 16KB + 3 x (K 16KB + V 16KB) = 112KB.
// ---------------------------------------------------------------------------
#define AQ_BYTES  16384
#define AST_SZ    32768            // K 16KB + V 16KB (128 rows each)
#define ATTN_SMEM (AQ_BYTES + 3 * AST_SZ + 128)
#define CEXP 0.18033688011112042f  // 0.125 * log2(e)

__global__ __launch_bounds__(256, 2)
void attn_mma_kernel(const __half* __restrict__ Qg, const __half* __restrict__ Kg,
                     const __half* __restrict__ Vg, __half* __restrict__ O) {
    extern __shared__ char dsm[];
    uint32_t base = smem_u32(dsm);
    base = (base + 127) & ~127u;

    int tid = threadIdx.x, lane = tid & 31, w = tid >> 5;
    int gq = lane >> 2, tig = lane & 3;
    int qi = gridDim.x - 1 - blockIdx.x;
    int q0 = qi * 128;
    int bh = blockIdx.y;
    int b = bh >> 4, h = bh & 15;
    size_t gbase = ((size_t)b * T_) * E_ + (size_t)h * HS_;

    int nt = (q0 >> 7) + 1;   // 128-key tiles covering [0, q0+128)

    cpa_tile128(Qg + gbase + (size_t)q0 * E_, E_, 0, base);
    CP_COMMIT();
    int pre = nt < 2 ? nt : 2;
    for (int st = 0; st < pre; st++) {
        uint32_t s = base + AQ_BYTES + st * AST_SZ;
        size_t koff = gbase + (size_t)(st * 128) * E_;
        cpa_tile128(Kg + koff, E_, 0, s);
        cpa_tile128(Vg + koff, E_, 0, s + 16384);
        CP_COMMIT();
    }

    if (pre == 2) { CP_WAIT2(); } else { CP_WAIT1(); }
    __syncthreads();

    uint32_t qf[4][4];
    {
        int arow = w * 16 + (lane & 7) + ((lane & 8) ? 8 : 0);
        int asel = (lane >> 4) & 1;
        #pragma unroll
        for (int ks = 0; ks < 4; ks++) {
            uint32_t off = (uint32_t)(arow * 128 + (ks * 2 + asel) * 16);
            off ^= (off >> 3) & 0x70;
            ldm_x4(qf[ks], base + off);
        }
    }

    float Oa[8][4];
    #pragma unroll
    for (int s = 0; s < 8; s++)
        #pragma unroll
        for (int r = 0; r < 4; r++) Oa[s][r] = 0.f;
    float l0r = 0.f, l1r = 0.f;

    int kRowBase = (lane & 7) + ((lane >= 16) ? 8 : 0);
    int kChkSel  = (lane & 8) ? 1 : 0;
    int vRowBase = (lane & 7) + ((lane & 8) ? 8 : 0);
    int vColB    = ((lane >= 16) ? 16 : 0);

    for (int jt = 0; jt < nt; jt++) {
        if (jt + 1 < nt) { CP_WAIT1(); } else { CP_WAIT0(); }
        __syncthreads();

        uint32_t sc = base + AQ_BYTES + (jt % 3) * AST_SZ;
        uint32_t sK = sc, sV = sc + 16384;
        bool edge = (jt == nt - 1);

        #pragma unroll
        for (int h2 = 0; h2 < 2; h2++) {
            // last tile, upper half: warps 0-3 fully masked
            if (edge && h2 == 1 && w < 4) continue;
            int rowOff = h2 * 64;

            float S[8][4];
            #pragma unroll
            for (int s = 0; s < 8; s++)
                #pragma unroll
                for (int r = 0; r < 4; r++) S[s][r] = 0.f;

            #pragma unroll
            for (int ks = 0; ks < 4; ks++) {
                #pragma unroll
                for (int g = 0; g < 4; g++) {
                    uint32_t k4[4];
                    uint32_t off = (uint32_t)((rowOff + g * 16 + kRowBase) * 128 +
                                              (ks * 2 + kChkSel) * 16);
                    off ^= (off >> 3) & 0x70;
                    ldm_x4(k4, sK + off);
                    mma16816h(S[2 * g],     qf[ks], &k4[0]);
                    mma16816h(S[2 * g + 1], qf[ks], &k4[2]);
                }
            }

            if (edge) {
                int qr0 = q0 + w * 16 + gq;
                int kc0 = jt * 128 + rowOff + 2 * tig;
                #pragma unroll
                for (int s = 0; s < 8; s++) {
                    int kc = kc0 + s * 8;
                    if (kc     > qr0)     S[s][0] = -1e30f;
                    if (kc + 1 > qr0)     S[s][1] = -1e30f;
                    if (kc     > qr0 + 8) S[s][2] = -1e30f;
                    if (kc + 1 > qr0 + 8) S[s][3] = -1e30f;
                }
            }

            uint32_t pa[4][4];
            float ls0 = 0.f, ls1 = 0.f;
            #pragma unroll
            for (int kk = 0; kk < 4; kk++) {
                #pragma unroll
                for (int half_ = 0; half_ < 2; half_++) {
                    float* Sr = S[2 * kk + half_];
                    __half2 e0 = h2exp2(__floats2half2_rn(Sr[0] * CEXP, Sr[1] * CEXP));
                    __half2 e1 = h2exp2(__floats2half2_rn(Sr[2] * CEXP, Sr[3] * CEXP));
                    pa[kk][half_ * 2 + 0] = *reinterpret_cast<uint32_t*>(&e0);
                    pa[kk][half_ * 2 + 1] = *reinterpret_cast<uint32_t*>(&e1);
                    float2 f0 = __half22float2(e0);
                    float2 f1 = __half22float2(e1);
                    ls0 += f0.x + f0.y;
                    ls1 += f1.x + f1.y;
                }
            }
            l0r += ls0;
            l1r += ls1;

            #pragma unroll
            for (int kk = 0; kk < 4; kk++) {
                #pragma unroll
                for (int g = 0; g < 4; g++) {
                    uint32_t v4[4];
                    uint32_t off = (uint32_t)((rowOff + kk * 16 + vRowBase) * 128 +
                                              g * 32 + vColB);
                    off ^= (off >> 3) & 0x70;
                    ldm_x4_t(v4, sV + off);
                    mma16816h(Oa[2 * g],     pa[kk], &v4[0]);
                    mma16816h(Oa[2 * g + 1], pa[kk], &v4[2]);
                }
            }
        }

        if (jt + 2 < nt) {
            uint32_t sn = base + AQ_BYTES + ((jt + 2) % 3) * AST_SZ;
            size_t koff = gbase + (size_t)((jt + 2) * 128) * E_;
            cpa_tile128(Kg + koff, E_, 0, sn);
            cpa_tile128(Vg + koff, E_, 0, sn + 16384);
            CP_COMMIT();
        }
    }

    l0r += __shfl_xor_sync(0xffffffffu, l0r, 1);
    l0r += __shfl_xor_sync(0xffffffffu, l0r, 2);
    l1r += __shfl_xor_sync(0xffffffffu, l1r, 1);
    l1r += __shfl_xor_sync(0xffffffffu, l1r, 2);

    float inv0 = 1.0f / l0r, inv1 = 1.0f / l1r;
    int row0 = q0 + w * 16 + gq;
    #pragma unroll
    for (int s = 0; s < 8; s++) {
        int col = s * 8 + 2 * tig;
        size_t o0 = gbase + (size_t)row0 * E_ + col;
        size_t o1 = gbase + (size_t)(row0 + 8) * E_ + col;
        *reinterpret_cast<uint32_t*>(O + o0) = pack_h2(Oa[s][0] * inv0, Oa[s][1] * inv0);
        *reinterpret_cast<uint32_t*>(O + o1) = pack_h2(Oa[s][2] * inv1, Oa[s][3] * inv1);
    }
}

// ---------------------------------------------------------------------------
// Launch
// ---------------------------------------------------------------------------
extern "C" void kernel_launch(void* const* d_in, const int* in_sizes, int n_in,
                              void* d_out, int out_size) {
    (void)in_sizes; (void)n_in; (void)out_size;
    const float* x     = (const float*)d_in[0];
    const float* ln1_g = (const float*)d_in[1];
    const float* ln1_b = (const float*)d_in[2];
    const float* Wq    = (const float*)d_in[3];
    const float* bq    = (const float*)d_in[4];
    const float* Wk    = (const float*)d_in[5];
    const float* bk    = (const float*)d_in[6];
    const float* Wv    = (const float*)d_in[7];
    const float* bv    = (const float*)d_in[8];
    const float* Wp    = (const float*)d_in[9];
    const float* bp    = (const float*)d_in[10];
    const float* ln2_g = (const float*)d_in[11];
    const float* ln2_b = (const float*)d_in[12];
    const float* W1    = (const float*)d_in[13];
    const float* b1    = (const float*)d_in[14];
    const float* W2    = (const float*)d_in[15];
    const float* b2    = (const float*)d_in[16];
    float* out = (float*)d_out;

    __half *a, *f, *q, *k, *v, *wq, *wk, *wv, *wp, *w1, *w2;
    cudaGetSymbolAddress((void**)&a, g_a);
    cudaGetSymbolAddress((void**)&f, g_f);
    cudaGetSymbolAddress((void**)&q, g_q);
    cudaGetSymbolAddress((void**)&k, g_k);
    cudaGetSymbolAddress((void**)&v, g_v);
    cudaGetSymbolAddress((void**)&wq, g_wq);
    cudaGetSymbolAddress((void**)&wk, g_wk);
    cudaGetSymbolAddress((void**)&wv, g_wv);
    cudaGetSymbolAddress((void**)&wp, g_wp);
    cudaGetSymbolAddress((void**)&w1, g_w1);
    cudaGetSymbolAddress((void**)&w2, g_w2);

    __half* r1 = q;   // fp16 residual stream (g_q free after attention)

    cudaFuncSetAttribute(attn_mma_kernel,
                         cudaFuncAttributeMaxDynamicSharedMemorySize, ATTN_SMEM);
    cudaFuncSetAttribute(hgemm_kernel<1>,
                         cudaFuncAttributeMaxDynamicSharedMemorySize, HGSMEM);
    cudaFuncSetAttribute(hgemm_kernel<3>,
                         cudaFuncAttributeMaxDynamicSharedMemorySize, HGSMEM);
    cudaFuncSetAttribute(hgemm_kernel<4>,
                         cudaFuncAttributeMaxDynamicSharedMemorySize, HGSMEM);
    cudaFuncSetAttribute(qkv_kernel,
                         cudaFuncAttributeMaxDynamicSharedMemorySize, HGSMEM);

    // fused prep: weight transposes + ln1 in one launch
    PrepArgs pa;
    pa.src[0] = Wq; pa.dst[0] = wq; pa.K[0] = E_;   pa.N[0] = E_;   pa.base[0] = 0;    pa.nx[0] = 16;
    pa.src[1] = Wk; pa.dst[1] = wk; pa.K[1] = E_;   pa.N[1] = E_;   pa.base[1] = 256;  pa.nx[1] = 16;
    pa.src[2] = Wv; pa.dst[2] = wv; pa.K[2] = E_;   pa.N[2] = E_;   pa.base[2] = 512;  pa.nx[2] = 16;
    pa.src[3] = Wp; pa.dst[3] = wp; pa.K[3] = E_;   pa.N[3] = E_;   pa.base[3] = 768;  pa.nx[3] = 16;
    pa.src[4] = W1; pa.dst[4] = w1; pa.K[4] = E_;   pa.N[4] = DFF_; pa.base[4] = 1024; pa.nx[4] = 64;
    pa.src[5] = W2; pa.dst[5] = w2; pa.K[5] = DFF_; pa.N[5] = E_;   pa.base[5] = 2048; pa.nx[5] = 16;
    pa.x = x; pa.ln_g = ln1_g; pa.ln_b = ln1_b; pa.ln_o = a;
    prep_kernel<<<WT_BLOCKS + M_, 256>>>(pa);

    // fused QKV
    QKVArgs qa;
    qa.w[0] = wq; qa.bias[0] = bq; qa.o[0] = q;
    qa.w[1] = wk; qa.bias[1] = bk; qa.o[1] = k;
    qa.w[2] = wv; qa.bias[2] = bv; qa.o[2] = v;
    dim3 gQKV(E_ / 128, M_ / 128, 3);
    qkv_kernel<<<gQKV, 256, HGSMEM>>>(a, qa);

    // attention -> a
    dim3 gA(T_ / 128, B_ * H_);
    attn_mma_kernel<<<gA, 256, ATTN_SMEM>>>(q, k, v, a);

    // proj + residual(x fp32) -> r1 (fp16 residual stream)
    dim3 gE(E_ / 128, M_ / 128);
    hgemm_kernel<3><<<gE, 256, HGSMEM>>>(a, wp, bp, x, nullptr, nullptr, r1,
                                         M_, E_, E_);

    // ln2 (fp16 in) -> fp16
    ln_h16_kernel<<<M_, 256>>>(r1, ln2_g, ln2_b, a);

    // FFN1 (relu -> fp16)
    dim3 gF1(DFF_ / 128, M_ / 128);
    hgemm_kernel<1><<<gF1, 256, HGSMEM>>>(a, w1, b1, nullptr, nullptr, nullptr, f,
                                          M_, DFF_, E_);

    // FFN2 + residual(r1 fp16) -> out (fp32)
    hgemm_kernel<4><<<gE, 256, HGSMEM>>>(f, w2, b2, nullptr, r1, out, nullptr,
                                         M_, E_, DFF_);
}